// round 3
// baseline (speedup 1.0000x reference)
#include <cuda_runtime.h>
#include <cuda_bf16.h>
#include <cstdint>

// out[b,s,d] = keep ? (emb[x[b,s],d] + pe[s,d]) * (1/0.9) : 0
// keep from JAX threefry2x32 (partitionable): key=(0,42), ctr=(0,i),
// bits = out0^out1, keep <=> bits < 0xE6666600  (== u<0.9f exactly)

// 2^r multipliers for all 8 distinct rotations; constant memory keeps them
// opaque (no strength reduction back to SHF) and uniform-register friendly.
__constant__ uint32_t ROTM[8] = {
    1u << 13, 1u << 15, 1u << 26, 1u << 6,
    1u << 17, 1u << 29, 1u << 16, 1u << 24
};

// rotl(x1,r)^x0 via IMAD.WIDE (fma pipe) + single 3-input LOP3 (alu pipe).
__device__ __forceinline__ void R_w(uint32_t& x0, uint32_t& x1, uint32_t m) {
    x0 += x1;
    unsigned long long p;
    asm("mul.wide.u32 %0, %1, %2;" : "=l"(p) : "r"(x1), "r"(m));
    x1 = ((uint32_t)p | (uint32_t)(p >> 32)) ^ x0;   // one LOP3
}

__device__ __forceinline__ uint32_t tf_bits(uint32_t ctr, const uint32_t* m) {
    const uint32_t ks1 = 42u;
    const uint32_t ks2 = 0x1BD11BF0u;  // 0 ^ 42 ^ 0x1BD11BDA
    uint32_t x0 = 0u;
    uint32_t x1 = ctr + ks1;
    R_w(x0, x1, m[0]); R_w(x0, x1, m[1]); R_w(x0, x1, m[2]); R_w(x0, x1, m[3]);
    x0 += ks1; x1 += ks2 + 1u;
    R_w(x0, x1, m[4]); R_w(x0, x1, m[5]); R_w(x0, x1, m[6]); R_w(x0, x1, m[7]);
    x0 += ks2; x1 += 2u;               // ks0 == 0
    R_w(x0, x1, m[0]); R_w(x0, x1, m[1]); R_w(x0, x1, m[2]); R_w(x0, x1, m[3]);
    /* x0 += ks0 (no-op) */ x1 += ks1 + 3u;
    R_w(x0, x1, m[4]); R_w(x0, x1, m[5]); R_w(x0, x1, m[6]); R_w(x0, x1, m[7]);
    x0 += ks1; x1 += ks2 + 4u;
    R_w(x0, x1, m[0]); R_w(x0, x1, m[1]); R_w(x0, x1, m[2]); R_w(x0, x1, m[3]);
    x0 += ks2; x1 += 5u;               // ks0 == 0
    return x0 ^ x1;
}

// 256 threads x 8 elems = 2048 elems = exactly two (b,s) rows per block.
__global__ __launch_bounds__(256) void embed_pe_drop_kernel(
    const int* __restrict__ x,
    const float* __restrict__ emb,
    float* __restrict__ out)
{
    uint32_t m[8];
#pragma unroll
    for (int k = 0; k < 8; k++) m[k] = ROTM[k];

    const uint32_t j = (blockIdx.x * 256u + threadIdx.x) * 8u;  // flat elem idx
    const uint32_t d = j & 1023u;
    const uint32_t row = j >> 10;       // b*2048 + s
    const uint32_t s = row & 2047u;

    const int tok = __ldg(x + row);
    const float* erow = emb + ((size_t)tok << 10) + d;
    const float4 eA = *reinterpret_cast<const float4*>(erow);
    const float4 eB = *reinterpret_cast<const float4*>(erow + 4);
    float ev[8] = {eA.x, eA.y, eA.z, eA.w, eB.x, eB.y, eB.z, eB.w};

    // pe[s,2i]=sin(s*10000^(-i/512)), pe[s,2i+1]=cos(...); angle in turns.
    const float KNEG   = -0.02595256324130752f;   // -log2(10000)/512
    const float STEP   = 0.98217188542871857f;    // 2^KNEG
    const float INV2PI = 0.15915494309189535f;
    const float TWOPI  = 6.2831853071795865f;
    const float sf = (float)s;
    float w = exp2f((float)(d >> 1) * KNEG) * INV2PI;
    float pe[8];
#pragma unroll
    for (int p = 0; p < 4; p++) {
        float t = sf * w;
        float fr = t - rintf(t);        // [-0.5, 0.5] turns
        float a = fr * TWOPI;
        pe[2 * p]     = __sinf(a);
        pe[2 * p + 1] = __cosf(a);
        w *= STEP;
    }

    // 8 independent threefry chains (ILP)
    uint32_t bits[8];
#pragma unroll
    for (int k = 0; k < 8; k++) bits[k] = tf_bits(j + (uint32_t)k, m);

    float o[8];
#pragma unroll
    for (int k = 0; k < 8; k++)
        o[k] = (bits[k] < 0xE6666600u) ? (ev[k] + pe[k]) * (1.0f / 0.9f) : 0.0f;

    float4* po = reinterpret_cast<float4*>(out + j);
    po[0] = make_float4(o[0], o[1], o[2], o[3]);
    po[1] = make_float4(o[4], o[5], o[6], o[7]);
}

extern "C" void kernel_launch(void* const* d_in, const int* in_sizes, int n_in,
                              void* d_out, int out_size) {
    const int* x;
    const float* emb;
    if (in_sizes[0] == 8 * 2048) {
        x = (const int*)d_in[0];
        emb = (const float*)d_in[1];
    } else {
        x = (const int*)d_in[1];
        emb = (const float*)d_in[0];
    }
    float* out = (float*)d_out;

    const int total = 8 * 2048 * 1024;        // 16,777,216
    const int threads = 256;
    const int blocks = total / (threads * 8); // 8192

    embed_pe_drop_kernel<<<blocks, threads>>>(x, emb, out);
}

// round 4
// speedup vs baseline: 1.1585x; 1.1585x over previous
#include <cuda_runtime.h>
#include <cuda_bf16.h>
#include <cstdint>

// out[b,s,d] = keep ? (emb[x[b,s],d] + pe[s,d]) * (1/0.9) : 0
// keep from JAX threefry2x32 (partitionable): key=(0,42), ctr=(0,i),
// bits = out0^out1, keep <=> bits < 0xE6666600  (== u<0.9f exactly)

// 2^r multipliers for the IMAD.WIDE rotate trick (opaque via __constant__).
__constant__ uint32_t ROTM[4] = {1u << 13, 1u << 26, 1u << 17, 1u << 16};

#define KS1 42u
#define KS2 0x1BD11BF0u

// Wide round on 4 interleaved chains: IADD3 + IMAD.WIDE(fma) + LOP3(alu)
#define W4(mm)                                                         \
    _Pragma("unroll") for (int k = 0; k < 4; k++) {                    \
        x0[k] += x1[k];                                                \
        unsigned long long p;                                          \
        asm("mul.wide.u32 %0, %1, %2;" : "=l"(p) : "r"(x1[k]), "r"(mm)); \
        x1[k] = ((uint32_t)p | (uint32_t)(p >> 32)) ^ x0[k];           \
    }

// Shift round on 4 interleaved chains: IADD3 + SHF(alu) + LOP3(alu)
#define S4(rr)                                                         \
    _Pragma("unroll") for (int k = 0; k < 4; k++) {                    \
        x0[k] += x1[k];                                                \
        x1[k] = __funnelshift_l(x1[k], x1[k], (rr)) ^ x0[k];           \
    }

__device__ __forceinline__ void tf_bits4(uint32_t ctr, uint32_t m13,
                                         uint32_t m26, uint32_t m17,
                                         uint32_t m16, uint32_t* bits) {
    uint32_t x0[4], x1[4];
#pragma unroll
    for (int k = 0; k < 4; k++) { x0[k] = 0u; x1[k] = ctr + (uint32_t)k + KS1; }
    W4(m13) S4(15) W4(m26) S4(6)
#pragma unroll
    for (int k = 0; k < 4; k++) { x0[k] += KS1; x1[k] += KS2 + 1u; }
    W4(m17) S4(29) W4(m16) S4(24)
#pragma unroll
    for (int k = 0; k < 4; k++) { x0[k] += KS2; x1[k] += 2u; }
    W4(m13) S4(15) W4(m26) S4(6)
#pragma unroll
    for (int k = 0; k < 4; k++) { x1[k] += KS1 + 3u; }   // ks0 == 0
    W4(m17) S4(29) W4(m16) S4(24)
#pragma unroll
    for (int k = 0; k < 4; k++) { x0[k] += KS1; x1[k] += KS2 + 4u; }
    W4(m13) S4(15) W4(m26) S4(6)
#pragma unroll
    for (int k = 0; k < 4; k++) { bits[k] = (x0[k] + KS2) ^ (x1[k] + 5u); }
}

// Block = one sequence position s (blockIdx.x), all 8 batches.
// 256 threads x 4 elems cover d in [0,1024); loop b = 0..7 reuses PE.
__global__ __launch_bounds__(256) void embed_pe_drop_kernel(
    const int* __restrict__ x,
    const float* __restrict__ emb,
    float* __restrict__ out)
{
    const uint32_t m13 = ROTM[0], m26 = ROTM[1], m17 = ROTM[2], m16 = ROTM[3];

    const uint32_t s = blockIdx.x;          // 0..2047
    const uint32_t d = threadIdx.x * 4u;    // 0..1020

    // PE once per thread: pe[s,2i]=sin(ang), pe[s,2i+1]=cos(ang)
    const float KNEG   = -0.02595256324130752f;   // -log2(10000)/512
    const float STEP   = 0.98217188542871857f;    // 2^KNEG
    const float INV2PI = 0.15915494309189535f;
    const float TWOPI  = 6.2831853071795865f;
    const float sf = (float)s;
    const float w0 = exp2f((float)(d >> 1) * KNEG) * INV2PI;
    const float w1 = w0 * STEP;
    float pe[4];
    {
        float t0 = sf * w0, t1 = sf * w1;
        float a0 = (t0 - rintf(t0)) * TWOPI;
        float a1 = (t1 - rintf(t1)) * TWOPI;
        pe[0] = __sinf(a0); pe[1] = __cosf(a0);
        pe[2] = __sinf(a1); pe[3] = __cosf(a1);
    }

    // Preload 8 token ids (block-uniform -> broadcast loads).
    int tok[8];
#pragma unroll
    for (int b = 0; b < 8; b++) tok[b] = __ldg(x + (b << 11) + s);

#pragma unroll
    for (int b = 0; b < 8; b++) {
        const uint32_t j = (((uint32_t)(b << 11) + s) << 10) + d;  // flat idx
        const float4 e = *reinterpret_cast<const float4*>(
            emb + ((size_t)tok[b] << 10) + d);

        uint32_t bits[4];
        tf_bits4(j, m13, m26, m17, m16, bits);

        float4 y;
        y.x = (bits[0] < 0xE6666600u) ? (e.x + pe[0]) * (1.0f / 0.9f) : 0.0f;
        y.y = (bits[1] < 0xE6666600u) ? (e.y + pe[1]) * (1.0f / 0.9f) : 0.0f;
        y.z = (bits[2] < 0xE6666600u) ? (e.z + pe[2]) * (1.0f / 0.9f) : 0.0f;
        y.w = (bits[3] < 0xE6666600u) ? (e.w + pe[3]) * (1.0f / 0.9f) : 0.0f;

        *reinterpret_cast<float4*>(out + j) = y;
    }
}

extern "C" void kernel_launch(void* const* d_in, const int* in_sizes, int n_in,
                              void* d_out, int out_size) {
    const int* x;
    const float* emb;
    if (in_sizes[0] == 8 * 2048) {
        x = (const int*)d_in[0];
        emb = (const float*)d_in[1];
    } else {
        x = (const int*)d_in[1];
        emb = (const float*)d_in[0];
    }
    float* out = (float*)d_out;

    embed_pe_drop_kernel<<<2048, 256>>>(x, emb, out);
}